// round 1
// baseline (speedup 1.0000x reference)
#include <cuda_runtime.h>
#include <cuda_bf16.h>

// Problem constants (fixed by the reference)
#define B_    2
#define L_    512
#define D_    512
#define V_    32000
#define TWOV  64000
#define MAXM  4096          // padded max rows (B*N = 2606 -> pad 2688)
#define NT2   500           // 64000 / 128 column tiles in GEMM2

// GEMM tiling
#define BM 128
#define BN 128
#define BK 32
#define SMP 40              // padded smem row stride in bf16 (conflict-free frag loads)
#define SMPW (SMP/2)        // in 32-bit words

// ---------------- device scratch (static, no allocation) ----------------
static __device__ __align__(256) __nv_bfloat16 g_fbB[MAXM * 1024];
static __device__ __align__(256) __nv_bfloat16 g_w1B[1024 * 512];
static __device__ __align__(256) __nv_bfloat16 g_w2B[512 * TWOV];
static __device__ __align__(256) float         g_h32[MAXM * 512];
static __device__ __align__(256) __nv_bfloat16 g_hB [MAXM * 512];
static __device__ __align__(256) float         g_pm [MAXM * NT2];
static __device__ __align__(256) float         g_ps [MAXM * NT2];
static __device__ __align__(256) float         g_nll[MAXM * 2];

// ---------------- fp32 -> bf16 weight conversion ----------------
__global__ void k_f2bf(const float* __restrict__ src, int which, int n4) {
    __nv_bfloat16* dst = which ? g_w2B : g_w1B;
    int i = blockIdx.x * blockDim.x + threadIdx.x;
    int stride = gridDim.x * blockDim.x;
    for (; i < n4; i += stride) {
        float4 v = reinterpret_cast<const float4*>(src)[i];
        __nv_bfloat162 lo = __floats2bfloat162_rn(v.x, v.y);
        __nv_bfloat162 hi = __floats2bfloat162_rn(v.z, v.w);
        reinterpret_cast<__nv_bfloat162*>(dst)[2 * i]     = lo;
        reinterpret_cast<__nv_bfloat162*>(dst)[2 * i + 1] = hi;
    }
}

// ---------------- gather fb = [fwd[b,fi], bwd[b,bi]] -> bf16, zero-pad ----------------
__global__ void k_gather(const float* __restrict__ fwd, const float* __restrict__ bwd,
                         const int* __restrict__ fi, const int* __restrict__ bi,
                         int Np, int M) {
    int row = blockIdx.x;
    if (row < M) {
        int b = row / Np;
        int n = row - b * Np;
        int f = fi[n];
        int bb = bi[n];
        const float* fsrc = fwd + ((size_t)b * L_ + f) * D_;
        const float* bsrc = bwd + ((size_t)b * L_ + bb) * D_;
        for (int c = threadIdx.x; c < 1024; c += blockDim.x) {
            float v = (c < 512) ? fsrc[c] : bsrc[c - 512];
            g_fbB[(size_t)row * 1024 + c] = __float2bfloat16(v);
        }
    } else {
        for (int c = threadIdx.x; c < 1024; c += blockDim.x)
            g_fbB[(size_t)row * 1024 + c] = __float2bfloat16(0.f);
    }
}

// ---------------- mma helper ----------------
__device__ __forceinline__ void mma16816(float c[4], const unsigned a[4], const unsigned b[2]) {
    asm volatile(
        "mma.sync.aligned.m16n8k16.row.col.f32.bf16.bf16.f32 "
        "{%0,%1,%2,%3}, {%4,%5,%6,%7}, {%8,%9}, {%0,%1,%2,%3};\n"
        : "+f"(c[0]), "+f"(c[1]), "+f"(c[2]), "+f"(c[3])
        : "r"(a[0]), "r"(a[1]), "r"(a[2]), "r"(a[3]), "r"(b[0]), "r"(b[1]));
}

// ---------------- shared GEMM mainloop (128x128 tile, K in 32-chunks) ----------------
// A: row-major [*, lda] bf16.  Bmat: row-major [K, ldb] bf16 (tile stored transposed in smem).
__device__ __forceinline__ void gemm_tile(
    const __nv_bfloat16* __restrict__ A, int lda,
    const __nv_bfloat16* __restrict__ Bmat, int ldb,
    int K, int row0, int col0,
    __nv_bfloat16* As, __nv_bfloat16* Bs,
    float acc[4][4][4])
{
    const int tid  = threadIdx.x;
    const int lane = tid & 31;
    const int wid  = tid >> 5;
    const int wm = wid >> 2, wn = wid & 3;
    const int g = lane >> 2, q = lane & 3;

#pragma unroll
    for (int a = 0; a < 4; a++)
#pragma unroll
        for (int b = 0; b < 4; b++)
#pragma unroll
            for (int c = 0; c < 4; c++) acc[a][b][c] = 0.f;

    const int KT = K >> 5;
    uint4 pa[2], pb[2];

    // prologue: load tile 0
#pragma unroll
    for (int i = 0; i < 2; i++) {
        int idx = tid + i * 256;
        pa[i] = *reinterpret_cast<const uint4*>(A + (size_t)(row0 + (idx >> 2)) * lda + ((idx & 3) << 3));
        pb[i] = *reinterpret_cast<const uint4*>(Bmat + (size_t)(idx >> 4) * ldb + col0 + ((idx & 15) << 3));
    }
#pragma unroll
    for (int i = 0; i < 2; i++) {
        int idx = tid + i * 256;
        *reinterpret_cast<uint4*>(As + (idx >> 2) * SMP + ((idx & 3) << 3)) = pa[i];
        __nv_bfloat16 tmp[8];
        *reinterpret_cast<uint4*>(tmp) = pb[i];
        int kr = idx >> 4, nc = idx & 15;
#pragma unroll
        for (int e = 0; e < 8; e++) Bs[(nc * 8 + e) * SMP + kr] = tmp[e];
    }
    __syncthreads();

    for (int kt = 0; kt < KT; kt++) {
        if (kt + 1 < KT) {
#pragma unroll
            for (int i = 0; i < 2; i++) {
                int idx = tid + i * 256;
                pa[i] = *reinterpret_cast<const uint4*>(
                    A + (size_t)(row0 + (idx >> 2)) * lda + (kt + 1) * BK + ((idx & 3) << 3));
                pb[i] = *reinterpret_cast<const uint4*>(
                    Bmat + (size_t)((kt + 1) * BK + (idx >> 4)) * ldb + col0 + ((idx & 15) << 3));
            }
        }
        const unsigned* As32 = reinterpret_cast<const unsigned*>(As);
        const unsigned* Bs32 = reinterpret_cast<const unsigned*>(Bs);
#pragma unroll
        for (int ks = 0; ks < 2; ks++) {
            unsigned afr[4][4], bfr[4][2];
#pragma unroll
            for (int mf = 0; mf < 4; mf++) {
                int row = wm * 64 + mf * 16 + g;
                int base = row * SMPW + ks * 8 + q;
                afr[mf][0] = As32[base];
                afr[mf][1] = As32[base + 8 * SMPW];
                afr[mf][2] = As32[base + 4];
                afr[mf][3] = As32[base + 8 * SMPW + 4];
            }
#pragma unroll
            for (int nf = 0; nf < 4; nf++) {
                int nn = wn * 32 + nf * 8 + g;
                int base = nn * SMPW + ks * 8 + q;
                bfr[nf][0] = Bs32[base];
                bfr[nf][1] = Bs32[base + 4];
            }
#pragma unroll
            for (int mf = 0; mf < 4; mf++)
#pragma unroll
                for (int nf = 0; nf < 4; nf++)
                    mma16816(acc[mf][nf], afr[mf], bfr[nf]);
        }
        __syncthreads();
        if (kt + 1 < KT) {
#pragma unroll
            for (int i = 0; i < 2; i++) {
                int idx = tid + i * 256;
                *reinterpret_cast<uint4*>(As + (idx >> 2) * SMP + ((idx & 3) << 3)) = pa[i];
                __nv_bfloat16 tmp[8];
                *reinterpret_cast<uint4*>(tmp) = pb[i];
                int kr = idx >> 4, nc = idx & 15;
#pragma unroll
                for (int e = 0; e < 8; e++) Bs[(nc * 8 + e) * SMP + kr] = tmp[e];
            }
            __syncthreads();
        }
    }
}

// ---------------- GEMM1: h = leaky_relu(fb @ w1 + b1) ----------------
__global__ __launch_bounds__(256, 1) void k_gemm1(const float* __restrict__ b1) {
    __shared__ __align__(16) __nv_bfloat16 As[BM * SMP];
    __shared__ __align__(16) __nv_bfloat16 Bs[BN * SMP];
    float acc[4][4][4];
    int row0 = blockIdx.y * BM, col0 = blockIdx.x * BN;
    gemm_tile(g_fbB, 1024, g_w1B, 512, 1024, row0, col0, As, Bs, acc);

    const int lane = threadIdx.x & 31, wid = threadIdx.x >> 5;
    const int wm = wid >> 2, wn = wid & 3, g = lane >> 2, q = lane & 3;
#pragma unroll
    for (int mf = 0; mf < 4; mf++) {
#pragma unroll
        for (int nf = 0; nf < 4; nf++) {
            int cl = col0 + wn * 32 + nf * 8 + q * 2;
#pragma unroll
            for (int i = 0; i < 4; i++) {
                int rr = row0 + wm * 64 + mf * 16 + g + ((i >= 2) ? 8 : 0);
                int cc = cl + (i & 1);
                float v = acc[mf][nf][i] + b1[cc];
                v = v > 0.f ? v : 0.01f * v;
                g_h32[(size_t)rr * 512 + cc] = v;
                g_hB [(size_t)rr * 512 + cc] = __float2bfloat16(v);
            }
        }
    }
}

// ---------------- GEMM2: streaming logsumexp partials over logits tiles ----------------
__global__ __launch_bounds__(256, 1) void k_gemm2(const float* __restrict__ b2) {
    __shared__ __align__(16) __nv_bfloat16 As[BM * SMP];
    __shared__ __align__(16) __nv_bfloat16 Bs[BN * SMP];
    __shared__ float red_m[4][128];
    __shared__ float red_s[4][128];
    __shared__ float rowmax[128];
    float acc[4][4][4];
    int row0 = blockIdx.y * BM, col0 = blockIdx.x * BN;
    gemm_tile(g_hB, 512, g_w2B, TWOV, 512, row0, col0, As, Bs, acc);

    const int tid = threadIdx.x;
    const int lane = tid & 31, wid = tid >> 5;
    const int wm = wid >> 2, wn = wid & 3, g = lane >> 2, q = lane & 3;

    float bv[4][2];
#pragma unroll
    for (int nf = 0; nf < 4; nf++) {
        int cc = col0 + wn * 32 + nf * 8 + q * 2;
        bv[nf][0] = b2[cc];
        bv[nf][1] = b2[cc + 1];
    }

    // pass 1: per-row tile max
#pragma unroll
    for (int mf = 0; mf < 4; mf++) {
#pragma unroll
        for (int rh = 0; rh < 2; rh++) {
            float m = -1e30f;
#pragma unroll
            for (int nf = 0; nf < 4; nf++) {
                m = fmaxf(m, acc[mf][nf][rh * 2 + 0] + bv[nf][0]);
                m = fmaxf(m, acc[mf][nf][rh * 2 + 1] + bv[nf][1]);
            }
            m = fmaxf(m, __shfl_xor_sync(0xffffffffu, m, 1));
            m = fmaxf(m, __shfl_xor_sync(0xffffffffu, m, 2));
            if (q == 0) red_m[wn][wm * 64 + mf * 16 + rh * 8 + g] = m;
        }
    }
    __syncthreads();
    if (tid < 128)
        rowmax[tid] = fmaxf(fmaxf(red_m[0][tid], red_m[1][tid]),
                            fmaxf(red_m[2][tid], red_m[3][tid]));
    __syncthreads();

    // pass 2: per-row sumexp
#pragma unroll
    for (int mf = 0; mf < 4; mf++) {
#pragma unroll
        for (int rh = 0; rh < 2; rh++) {
            int rl = wm * 64 + mf * 16 + rh * 8 + g;
            float rm = rowmax[rl];
            float s = 0.f;
#pragma unroll
            for (int nf = 0; nf < 4; nf++) {
                s += expf(acc[mf][nf][rh * 2 + 0] + bv[nf][0] - rm);
                s += expf(acc[mf][nf][rh * 2 + 1] + bv[nf][1] - rm);
            }
            s += __shfl_xor_sync(0xffffffffu, s, 1);
            s += __shfl_xor_sync(0xffffffffu, s, 2);
            if (q == 0) red_s[wn][rl] = s;
        }
    }
    __syncthreads();
    if (tid < 128) {
        float s = red_s[0][tid] + red_s[1][tid] + red_s[2][tid] + red_s[3][tid];
        int rowg = row0 + tid;
        g_pm[(size_t)rowg * NT2 + blockIdx.x] = rowmax[tid];
        g_ps[(size_t)rowg * NT2 + blockIdx.x] = s;
    }
}

// ---------------- per-(row,branch) lse merge + label logit + nll ----------------
__global__ void k_reduce(const int* __restrict__ seq, const int* __restrict__ fi,
                         const int* __restrict__ bi, const float* __restrict__ w2,
                         const float* __restrict__ b2, int Np, int M) {
    int gw = (blockIdx.x * blockDim.x + threadIdx.x) >> 5;
    int lane = threadIdx.x & 31;
    if (gw >= M * 2) return;
    int r = gw >> 1, br = gw & 1;
    int b = r / Np, n = r - b * Np;
    int pos = br ? bi[n] : fi[n];
    int label = seq[b * L_ + pos];
    int col = br * V_ + label;

    const float* pm = g_pm + (size_t)r * NT2 + br * 250;
    const float* ps = g_ps + (size_t)r * NT2 + br * 250;
    float m = -1e30f;
    for (int i = lane; i < 250; i += 32) m = fmaxf(m, pm[i]);
#pragma unroll
    for (int o = 16; o; o >>= 1) m = fmaxf(m, __shfl_xor_sync(0xffffffffu, m, o));
    float s = 0.f;
    for (int i = lane; i < 250; i += 32) s += ps[i] * expf(pm[i] - m);
#pragma unroll
    for (int o = 16; o; o >>= 1) s += __shfl_xor_sync(0xffffffffu, s, o);
    float lse = m + logf(s);

    // label logit in full fp32
    float dot = 0.f;
    for (int k = lane; k < 512; k += 32)
        dot += g_h32[(size_t)r * 512 + k] * w2[(size_t)k * TWOV + col];
#pragma unroll
    for (int o = 16; o; o >>= 1) dot += __shfl_xor_sync(0xffffffffu, dot, o);

    if (lane == 0) {
        float nll = lse - (dot + b2[col]);
        g_nll[gw] = nll * (br ? 0.25f : 1.0f);
    }
}

// ---------------- deterministic final mean ----------------
__global__ void k_final(float* __restrict__ out, int M) {
    __shared__ float sh[256];
    float s = 0.f;
    for (int i = threadIdx.x; i < 2 * M; i += 256) s += g_nll[i];
    sh[threadIdx.x] = s;
    __syncthreads();
    for (int o = 128; o; o >>= 1) {
        if (threadIdx.x < o) sh[threadIdx.x] += sh[threadIdx.x + o];
        __syncthreads();
    }
    if (threadIdx.x == 0) out[0] = sh[0] / (float)(2 * M);
}

// ---------------- launch ----------------
extern "C" void kernel_launch(void* const* d_in, const int* in_sizes, int n_in,
                              void* d_out, int out_size) {
    const float* fwd = (const float*)d_in[0];
    const float* bwd = (const float*)d_in[1];
    const int*   seq = (const int*)  d_in[2];
    const int*   fi  = (const int*)  d_in[3];
    const int*   bi  = (const int*)  d_in[4];
    const float* w1  = (const float*)d_in[5];
    const float* b1  = (const float*)d_in[6];
    const float* w2  = (const float*)d_in[7];
    const float* b2  = (const float*)d_in[8];

    int Np = in_sizes[3];           // number of (fi,bi) pairs
    int M  = B_ * Np;               // rows
    int MT = (M + BM - 1) / BM;
    int Mpad = MT * BM;

    k_f2bf<<<256, 256>>>(w1, 0, (1024 * 512) / 4);
    k_f2bf<<<2048, 256>>>(w2, 1, (512 * TWOV) / 4);
    k_gather<<<Mpad, 256>>>(fwd, bwd, fi, bi, Np, M);

    dim3 g1(512 / BN, MT);
    k_gemm1<<<g1, 256>>>(b1);

    dim3 g2(NT2, MT);
    k_gemm2<<<g2, 256>>>(b2);

    int warps = M * 2;
    int blocks = (warps * 32 + 255) / 256;
    k_reduce<<<blocks, 256>>>(seq, fi, bi, w2, b2, Np, M);
    k_final<<<1, 256>>>((float*)d_out, M);
}

// round 2
// speedup vs baseline: 2.4402x; 2.4402x over previous
#include <cuda_runtime.h>
#include <cuda_bf16.h>

// Problem constants
#define B_    2
#define L_    512
#define V_    32000
#define TWOV  64000
#define MAXM  4096
#define NT2   500            // 64000/128 column tiles

// GEMM tiling
#define BM 128
#define BN 128
#define BK 32
#define SA 40                // A smem row stride (bf16): 32 + 8 pad  (80B, 16B-mult)
#define SB 136               // B smem row stride (bf16): 128 + 8 pad (272B, 16B-mult)
#define STAGES 4

#define A_ST (BM * SA * 2)   // 10240 B per A stage
#define B_ST (BK * SB * 2)   // 8704 B per B stage (gemm1 only)
#define G1_SMEM (STAGES * (A_ST + B_ST))          // 75776
#define B2_BYTES (512 * SB * 2)                   // 139264 (full B slice, gemm2)
#define G2_SCR   (B2_BYTES + STAGES * A_ST)       // 180224
#define G2_SMEM  (G2_SCR + 4608)                  // 184832

// ---------------- device scratch ----------------
static __device__ __align__(256) __nv_bfloat16 g_fbB[MAXM * 1024];
static __device__ __align__(256) __nv_bfloat16 g_w1B[1024 * 512];
static __device__ __align__(256) __nv_bfloat16 g_w2B[512 * TWOV];
static __device__ __align__(256) float         g_h32[MAXM * 512];
static __device__ __align__(256) __nv_bfloat16 g_hB [MAXM * 512];
static __device__ __align__(256) float         g_pm [MAXM * NT2];
static __device__ __align__(256) float         g_ps [MAXM * NT2];
static __device__ __align__(256) float         g_nll[MAXM * 2];

// ---------------- PTX helpers ----------------
__device__ __forceinline__ void cpa16(unsigned s, const void* g) {
    asm volatile("cp.async.cg.shared.global [%0], [%1], 16;\n" :: "r"(s), "l"(g));
}
__device__ __forceinline__ void cp_commit() { asm volatile("cp.async.commit_group;\n"); }
template<int N> __device__ __forceinline__ void cp_wait() {
    asm volatile("cp.async.wait_group %0;\n" :: "n"(N));
}
__device__ __forceinline__ void ldsmx4(unsigned* r, unsigned a) {
    asm volatile("ldmatrix.sync.aligned.m8n8.x4.shared.b16 {%0,%1,%2,%3}, [%4];\n"
                 : "=r"(r[0]), "=r"(r[1]), "=r"(r[2]), "=r"(r[3]) : "r"(a));
}
__device__ __forceinline__ void ldsmx4t(unsigned* r, unsigned a) {
    asm volatile("ldmatrix.sync.aligned.m8n8.x4.trans.shared.b16 {%0,%1,%2,%3}, [%4];\n"
                 : "=r"(r[0]), "=r"(r[1]), "=r"(r[2]), "=r"(r[3]) : "r"(a));
}
__device__ __forceinline__ void mma16816(float* c, const unsigned* a, const unsigned* b) {
    asm volatile(
        "mma.sync.aligned.m16n8k16.row.col.f32.bf16.bf16.f32 "
        "{%0,%1,%2,%3}, {%4,%5,%6,%7}, {%8,%9}, {%0,%1,%2,%3};\n"
        : "+f"(c[0]), "+f"(c[1]), "+f"(c[2]), "+f"(c[3])
        : "r"(a[0]), "r"(a[1]), "r"(a[2]), "r"(a[3]), "r"(b[0]), "r"(b[1]));
}

// ---------------- fp32 -> bf16 weight conversion ----------------
__global__ void k_f2bf(const float* __restrict__ src, int which, int n4) {
    __nv_bfloat16* dst = which ? g_w2B : g_w1B;
    int i = blockIdx.x * blockDim.x + threadIdx.x;
    int stride = gridDim.x * blockDim.x;
    for (; i < n4; i += stride) {
        float4 v = reinterpret_cast<const float4*>(src)[i];
        __nv_bfloat162 lo = __floats2bfloat162_rn(v.x, v.y);
        __nv_bfloat162 hi = __floats2bfloat162_rn(v.z, v.w);
        reinterpret_cast<__nv_bfloat162*>(dst)[2 * i]     = lo;
        reinterpret_cast<__nv_bfloat162*>(dst)[2 * i + 1] = hi;
    }
}

// ---------------- gather fb rows -> bf16, zero-pad ----------------
__global__ void k_gather(const float* __restrict__ fwd, const float* __restrict__ bwd,
                         const int* __restrict__ fi, const int* __restrict__ bi,
                         int Np, int M) {
    int row = blockIdx.x;
    if (row < M) {
        int b = row / Np;
        int n = row - b * Np;
        const float* fsrc = fwd + ((size_t)b * L_ + fi[n]) * 512;
        const float* bsrc = bwd + ((size_t)b * L_ + bi[n]) * 512;
        for (int c = threadIdx.x; c < 1024; c += blockDim.x) {
            float v = (c < 512) ? fsrc[c] : bsrc[c - 512];
            g_fbB[(size_t)row * 1024 + c] = __float2bfloat16(v);
        }
    } else {
        for (int c = threadIdx.x; c < 1024; c += blockDim.x)
            g_fbB[(size_t)row * 1024 + c] = __float2bfloat16(0.f);
    }
}

// ---------------- GEMM1: h = leaky_relu(fb @ w1 + b1) ----------------
__global__ __launch_bounds__(256) void k_gemm1(const float* __restrict__ b1) {
    extern __shared__ char smem[];
    unsigned sb = (unsigned)__cvta_generic_to_shared(smem);
    const unsigned A0 = sb;
    const unsigned B0 = sb + STAGES * A_ST;
    const int tid = threadIdx.x, lane = tid & 31, wid = tid >> 5;
    const int wm = wid >> 2, wn = wid & 3;
    const int row0 = blockIdx.y * BM, col0 = blockIdx.x * BN;

    const unsigned aoff = ((wm * 64 + (lane & 15)) * SA + (lane >> 4) * 8) * 2;
    const unsigned boff = ((lane & 15) * SB + wn * 32 + (lane >> 4) * 8) * 2;

    float acc[4][4][4];
#pragma unroll
    for (int a = 0; a < 4; a++)
#pragma unroll
        for (int b = 0; b < 4; b++)
#pragma unroll
            for (int c = 0; c < 4; c++) acc[a][b][c] = 0.f;

    auto loadAB = [&](int st, int kk) {
#pragma unroll
        for (int i = 0; i < 2; i++) {
            int r = i * 64 + (tid >> 2), c = (tid & 3) * 8;
            cpa16(A0 + st * A_ST + (unsigned)(r * SA + c) * 2,
                  g_fbB + (size_t)(row0 + r) * 1024 + kk * BK + c);
        }
#pragma unroll
        for (int i = 0; i < 2; i++) {
            int r = i * 16 + (tid >> 4), c = (tid & 15) * 8;
            cpa16(B0 + st * B_ST + (unsigned)(r * SB + c) * 2,
                  g_w1B + (size_t)(kk * BK + r) * 512 + col0 + c);
        }
    };

    const int KT = 1024 / BK;
#pragma unroll
    for (int s = 0; s < STAGES - 1; s++) { loadAB(s, s); cp_commit(); }

    for (int kt = 0; kt < KT; kt++) {
        cp_wait<STAGES - 2>();
        __syncthreads();
        int kl = kt + STAGES - 1;
        if (kl < KT) loadAB(kl & (STAGES - 1), kl);
        cp_commit();
        int st = kt & (STAGES - 1);
        unsigned aS = A0 + st * A_ST + aoff;
        unsigned bS = B0 + st * B_ST + boff;
#pragma unroll
        for (int ks = 0; ks < 2; ks++) {
            unsigned afr[4][4], bfr[2][4];
#pragma unroll
            for (int mf = 0; mf < 4; mf++) ldsmx4(afr[mf], aS + mf * (16 * SA * 2) + ks * 32);
#pragma unroll
            for (int p = 0; p < 2; p++) ldsmx4t(bfr[p], bS + ks * (16 * SB * 2) + p * 32);
#pragma unroll
            for (int mf = 0; mf < 4; mf++) {
                mma16816(acc[mf][0], afr[mf], &bfr[0][0]);
                mma16816(acc[mf][1], afr[mf], &bfr[0][2]);
                mma16816(acc[mf][2], afr[mf], &bfr[1][0]);
                mma16816(acc[mf][3], afr[mf], &bfr[1][2]);
            }
        }
    }

    const int g = lane >> 2, q = lane & 3;
#pragma unroll
    for (int mf = 0; mf < 4; mf++) {
#pragma unroll
        for (int nf = 0; nf < 4; nf++) {
            int cl = col0 + wn * 32 + nf * 8 + q * 2;
#pragma unroll
            for (int i = 0; i < 4; i++) {
                int rr = row0 + wm * 64 + mf * 16 + g + ((i >= 2) ? 8 : 0);
                int cc = cl + (i & 1);
                float v = acc[mf][nf][i] + b1[cc];
                v = v > 0.f ? v : 0.01f * v;
                g_h32[(size_t)rr * 512 + cc] = v;
                g_hB [(size_t)rr * 512 + cc] = __float2bfloat16(v);
            }
        }
    }
}

// ---------------- GEMM2: B-persistent, streaming logsumexp partials ----------------
__global__ __launch_bounds__(256) void k_gemm2(const float* __restrict__ b2, int MT) {
    extern __shared__ char smem[];
    unsigned sb = (unsigned)__cvta_generic_to_shared(smem);
    const unsigned Bb = sb;
    const unsigned Ab = sb + B2_BYTES;
    float* red_m  = (float*)(smem + G2_SCR);       // [4][128]
    float* red_s  = red_m + 512;                   // [4][128]
    float* rowmax = red_s + 512;                   // [128]

    const int tid = threadIdx.x, lane = tid & 31, wid = tid >> 5;
    const int wm = wid >> 2, wn = wid & 3;
    const int g = lane >> 2, q = lane & 3;
    const int ct = blockIdx.x;
    const int col0 = ct * BN;

    // Load the full 512x128 B slice once (group 0)
#pragma unroll
    for (int i = 0; i < 32; i++) {
        int r = i * 16 + (tid >> 4), c = (tid & 15) * 8;
        cpa16(Bb + (unsigned)(r * SB + c) * 2, g_w2B + (size_t)r * TWOV + col0 + c);
    }
    cp_commit();

    const unsigned aoff = ((wm * 64 + (lane & 15)) * SA + (lane >> 4) * 8) * 2;
    const unsigned boff = ((lane & 15) * SB + wn * 32 + (lane >> 4) * 8) * 2;

    float bv[4][2];
#pragma unroll
    for (int nf = 0; nf < 4; nf++) {
        int cc = col0 + wn * 32 + nf * 8 + q * 2;
        bv[nf][0] = b2[cc];
        bv[nf][1] = b2[cc + 1];
    }

    auto loadA = [&](int st, int kk, int row0) {
#pragma unroll
        for (int i = 0; i < 2; i++) {
            int r = i * 64 + (tid >> 2), c = (tid & 3) * 8;
            cpa16(Ab + st * A_ST + (unsigned)(r * SA + c) * 2,
                  g_hB + (size_t)(row0 + r) * 512 + kk * BK + c);
        }
    };

    const int KT = 512 / BK;  // 16
    for (int rb = 0; rb < MT; rb++) {
        int row0 = rb * BM;
        float acc[4][4][4];
#pragma unroll
        for (int a = 0; a < 4; a++)
#pragma unroll
            for (int b = 0; b < 4; b++)
#pragma unroll
                for (int c = 0; c < 4; c++) acc[a][b][c] = 0.f;

#pragma unroll
        for (int s = 0; s < STAGES - 1; s++) { loadA(s, s, row0); cp_commit(); }

        for (int kt = 0; kt < KT; kt++) {
            cp_wait<STAGES - 2>();
            __syncthreads();
            int kl = kt + STAGES - 1;
            if (kl < KT) loadA(kl & (STAGES - 1), kl, row0);
            cp_commit();
            int st = kt & (STAGES - 1);
            unsigned aS = Ab + st * A_ST + aoff;
            unsigned bS = Bb + (unsigned)(kt * BK * SB) * 2 + boff;
#pragma unroll
            for (int ks = 0; ks < 2; ks++) {
                unsigned afr[4][4], bfr[2][4];
#pragma unroll
                for (int mf = 0; mf < 4; mf++) ldsmx4(afr[mf], aS + mf * (16 * SA * 2) + ks * 32);
#pragma unroll
                for (int p = 0; p < 2; p++) ldsmx4t(bfr[p], bS + ks * (16 * SB * 2) + p * 32);
#pragma unroll
                for (int mf = 0; mf < 4; mf++) {
                    mma16816(acc[mf][0], afr[mf], &bfr[0][0]);
                    mma16816(acc[mf][1], afr[mf], &bfr[0][2]);
                    mma16816(acc[mf][2], afr[mf], &bfr[1][0]);
                    mma16816(acc[mf][3], afr[mf], &bfr[1][2]);
                }
            }
        }

        // ---- epilogue: per-row tile max + sumexp partials ----
        __syncthreads();   // all ldmatrix reads done; scratch safe to write
#pragma unroll
        for (int mf = 0; mf < 4; mf++) {
#pragma unroll
            for (int rh = 0; rh < 2; rh++) {
                float m = -1e30f;
#pragma unroll
                for (int nf = 0; nf < 4; nf++) {
                    m = fmaxf(m, acc[mf][nf][rh * 2 + 0] + bv[nf][0]);
                    m = fmaxf(m, acc[mf][nf][rh * 2 + 1] + bv[nf][1]);
                }
                m = fmaxf(m, __shfl_xor_sync(0xffffffffu, m, 1));
                m = fmaxf(m, __shfl_xor_sync(0xffffffffu, m, 2));
                if (q == 0) red_m[wn * 128 + wm * 64 + mf * 16 + rh * 8 + g] = m;
            }
        }
        __syncthreads();
        if (tid < 128)
            rowmax[tid] = fmaxf(fmaxf(red_m[tid], red_m[128 + tid]),
                                fmaxf(red_m[256 + tid], red_m[384 + tid]));
        __syncthreads();
#pragma unroll
        for (int mf = 0; mf < 4; mf++) {
#pragma unroll
            for (int rh = 0; rh < 2; rh++) {
                int rl = wm * 64 + mf * 16 + rh * 8 + g;
                float rm = rowmax[rl];
                float s = 0.f;
#pragma unroll
                for (int nf = 0; nf < 4; nf++) {
                    s += __expf(acc[mf][nf][rh * 2 + 0] + bv[nf][0] - rm);
                    s += __expf(acc[mf][nf][rh * 2 + 1] + bv[nf][1] - rm);
                }
                s += __shfl_xor_sync(0xffffffffu, s, 1);
                s += __shfl_xor_sync(0xffffffffu, s, 2);
                if (q == 0) red_s[wn * 128 + rl] = s;
            }
        }
        __syncthreads();
        if (tid < 128) {
            float s = red_s[tid] + red_s[128 + tid] + red_s[256 + tid] + red_s[384 + tid];
            int rowg = row0 + tid;
            g_pm[(size_t)rowg * NT2 + ct] = rowmax[tid];
            g_ps[(size_t)rowg * NT2 + ct] = s;
        }
        __syncthreads();
    }
}

// ---------------- per-(row,branch) lse merge + label logit + nll ----------------
__global__ void k_reduce(const int* __restrict__ seq, const int* __restrict__ fi,
                         const int* __restrict__ bi, const float* __restrict__ w2,
                         const float* __restrict__ b2, int Np, int M) {
    int gw = (blockIdx.x * blockDim.x + threadIdx.x) >> 5;
    int lane = threadIdx.x & 31;
    if (gw >= M * 2) return;
    int r = gw >> 1, br = gw & 1;
    int b = r / Np, n = r - b * Np;
    int pos = br ? bi[n] : fi[n];
    int label = seq[b * L_ + pos];
    int col = br * V_ + label;

    const float* pm = g_pm + (size_t)r * NT2 + br * 250;
    const float* ps = g_ps + (size_t)r * NT2 + br * 250;
    float m = -1e30f;
    for (int i = lane; i < 250; i += 32) m = fmaxf(m, pm[i]);
#pragma unroll
    for (int o = 16; o; o >>= 1) m = fmaxf(m, __shfl_xor_sync(0xffffffffu, m, o));
    float s = 0.f;
    for (int i = lane; i < 250; i += 32) s += ps[i] * __expf(pm[i] - m);
#pragma unroll
    for (int o = 16; o; o >>= 1) s += __shfl_xor_sync(0xffffffffu, s, o);
    float lse = m + logf(s);

    float dot = 0.f;
    for (int k = lane; k < 512; k += 32)
        dot += g_h32[(size_t)r * 512 + k] * w2[(size_t)k * TWOV + col];
#pragma unroll
    for (int o = 16; o; o >>= 1) dot += __shfl_xor_sync(0xffffffffu, dot, o);

    if (lane == 0) {
        float nll = lse - (dot + b2[col]);
        g_nll[gw] = nll * (br ? 0.25f : 1.0f);
    }
}

// ---------------- deterministic final mean ----------------
__global__ void k_final(float* __restrict__ out, int M) {
    __shared__ float sh[256];
    float s = 0.f;
    for (int i = threadIdx.x; i < 2 * M; i += 256) s += g_nll[i];
    sh[threadIdx.x] = s;
    __syncthreads();
    for (int o = 128; o; o >>= 1) {
        if (threadIdx.x < o) sh[threadIdx.x] += sh[threadIdx.x + o];
        __syncthreads();
    }
    if (threadIdx.x == 0) out[0] = sh[0] / (float)(2 * M);
}

// ---------------- launch ----------------
extern "C" void kernel_launch(void* const* d_in, const int* in_sizes, int n_in,
                              void* d_out, int out_size) {
    const float* fwd = (const float*)d_in[0];
    const float* bwd = (const float*)d_in[1];
    const int*   seq = (const int*)  d_in[2];
    const int*   fi  = (const int*)  d_in[3];
    const int*   bi  = (const int*)  d_in[4];
    const float* w1  = (const float*)d_in[5];
    const float* b1  = (const float*)d_in[6];
    const float* w2  = (const float*)d_in[7];
    const float* b2  = (const float*)d_in[8];

    int Np = in_sizes[3];
    int M  = B_ * Np;
    int MT = (M + BM - 1) / BM;
    int Mpad = MT * BM;

    cudaFuncSetAttribute(k_gemm1, cudaFuncAttributeMaxDynamicSharedMemorySize, G1_SMEM);
    cudaFuncSetAttribute(k_gemm2, cudaFuncAttributeMaxDynamicSharedMemorySize, G2_SMEM);

    k_f2bf<<<256, 256>>>(w1, 0, (1024 * 512) / 4);
    k_f2bf<<<2048, 256>>>(w2, 1, (512 * TWOV) / 4);
    k_gather<<<Mpad, 256>>>(fwd, bwd, fi, bi, Np, M);

    dim3 g1(512 / BN, MT);
    k_gemm1<<<g1, 256, G1_SMEM>>>(b1);

    k_gemm2<<<NT2, 256, G2_SMEM>>>(b2, MT);

    int warps = M * 2;
    int blocks = (warps * 32 + 255) / 256;
    k_reduce<<<blocks, 256>>>(seq, fi, bi, w2, b2, Np, M);
    k_final<<<1, 256>>>((float*)d_out, M);
}

// round 3
// speedup vs baseline: 2.4459x; 1.0023x over previous
#include <cuda_runtime.h>
#include <cuda_bf16.h>

// Problem constants
#define B_    2
#define L_    512
#define V_    32000
#define TWOV  64000
#define MAXM  4096
#define NT2   500            // 64000/128 column tiles

// GEMM tiling
#define BM 128
#define BN 128
#define BK 32
#define SA 40                // A smem row stride (bf16): 32 + 8 pad  (80B, 16B-mult)
#define SB 136               // B smem row stride (bf16): 128 + 8 pad (272B, 16B-mult)
#define STAGES 4

#define A_ST (BM * SA * 2)   // 10240 B per A stage
#define B_ST (BK * SB * 2)   // 8704 B per B stage (gemm1 only)
#define G1_SMEM (STAGES * (A_ST + B_ST))          // 75776
#define B2_BYTES (512 * SB * 2)                   // 139264 (full B slice, gemm2)
#define G2_SCR   (B2_BYTES + STAGES * A_ST)       // 180224
#define G2_SMEM  (G2_SCR + 4608)                  // 184832

// ---------------- device scratch ----------------
static __device__ __align__(256) __nv_bfloat16 g_fbB[MAXM * 1024];
static __device__ __align__(256) __nv_bfloat16 g_w1B[1024 * 512];
static __device__ __align__(256) __nv_bfloat16 g_w2B[512 * TWOV];
static __device__ __align__(256) float         g_h32[MAXM * 512];
static __device__ __align__(256) __nv_bfloat16 g_hB [MAXM * 512];
static __device__ __align__(256) float         g_pm [MAXM * NT2];
static __device__ __align__(256) float         g_ps [MAXM * NT2];
static __device__ __align__(256) float         g_nll[MAXM * 2];

// ---------------- PTX helpers ----------------
__device__ __forceinline__ void cpa16(unsigned s, const void* g) {
    asm volatile("cp.async.cg.shared.global [%0], [%1], 16;\n" :: "r"(s), "l"(g));
}
__device__ __forceinline__ void cp_commit() { asm volatile("cp.async.commit_group;\n"); }
template<int N> __device__ __forceinline__ void cp_wait() {
    asm volatile("cp.async.wait_group %0;\n" :: "n"(N));
}
__device__ __forceinline__ void ldsmx4(unsigned* r, unsigned a) {
    asm volatile("ldmatrix.sync.aligned.m8n8.x4.shared.b16 {%0,%1,%2,%3}, [%4];\n"
                 : "=r"(r[0]), "=r"(r[1]), "=r"(r[2]), "=r"(r[3]) : "r"(a));
}
__device__ __forceinline__ void ldsmx4t(unsigned* r, unsigned a) {
    asm volatile("ldmatrix.sync.aligned.m8n8.x4.trans.shared.b16 {%0,%1,%2,%3}, [%4];\n"
                 : "=r"(r[0]), "=r"(r[1]), "=r"(r[2]), "=r"(r[3]) : "r"(a));
}
__device__ __forceinline__ void mma16816(float* c, const unsigned* a, const unsigned* b) {
    asm volatile(
        "mma.sync.aligned.m16n8k16.row.col.f32.bf16.bf16.f32 "
        "{%0,%1,%2,%3}, {%4,%5,%6,%7}, {%8,%9}, {%0,%1,%2,%3};\n"
        : "+f"(c[0]), "+f"(c[1]), "+f"(c[2]), "+f"(c[3])
        : "r"(a[0]), "r"(a[1]), "r"(a[2]), "r"(a[3]), "r"(b[0]), "r"(b[1]));
}

// ---------------- fp32 -> bf16 weight conversion ----------------
__global__ void k_f2bf(const float* __restrict__ src, int which, int n4) {
    __nv_bfloat16* dst = which ? g_w2B : g_w1B;
    int i = blockIdx.x * blockDim.x + threadIdx.x;
    int stride = gridDim.x * blockDim.x;
    for (; i < n4; i += stride) {
        float4 v = reinterpret_cast<const float4*>(src)[i];
        __nv_bfloat162 lo = __floats2bfloat162_rn(v.x, v.y);
        __nv_bfloat162 hi = __floats2bfloat162_rn(v.z, v.w);
        reinterpret_cast<__nv_bfloat162*>(dst)[2 * i]     = lo;
        reinterpret_cast<__nv_bfloat162*>(dst)[2 * i + 1] = hi;
    }
}

// ---------------- gather fb rows -> bf16, zero-pad ----------------
__global__ void k_gather(const float* __restrict__ fwd, const float* __restrict__ bwd,
                         const int* __restrict__ fi, const int* __restrict__ bi,
                         int Np, int M) {
    int row = blockIdx.x;
    if (row < M) {
        int b = row / Np;
        int n = row - b * Np;
        const float* fsrc = fwd + ((size_t)b * L_ + fi[n]) * 512;
        const float* bsrc = bwd + ((size_t)b * L_ + bi[n]) * 512;
        for (int c = threadIdx.x; c < 1024; c += blockDim.x) {
            float v = (c < 512) ? fsrc[c] : bsrc[c - 512];
            g_fbB[(size_t)row * 1024 + c] = __float2bfloat16(v);
        }
    } else {
        for (int c = threadIdx.x; c < 1024; c += blockDim.x)
            g_fbB[(size_t)row * 1024 + c] = __float2bfloat16(0.f);
    }
}

// ---------------- GEMM1: h = leaky_relu(fb @ w1 + b1) ----------------
__global__ __launch_bounds__(256) void k_gemm1(const float* __restrict__ b1) {
    extern __shared__ char smem[];
    unsigned sb = (unsigned)__cvta_generic_to_shared(smem);
    const unsigned A0 = sb;
    const unsigned B0 = sb + STAGES * A_ST;
    const int tid = threadIdx.x, lane = tid & 31, wid = tid >> 5;
    const int wm = wid >> 2, wn = wid & 3;
    const int row0 = blockIdx.y * BM, col0 = blockIdx.x * BN;

    const unsigned aoff = ((wm * 64 + (lane & 15)) * SA + (lane >> 4) * 8) * 2;
    const unsigned boff = ((lane & 15) * SB + wn * 32 + (lane >> 4) * 8) * 2;

    float acc[4][4][4];
#pragma unroll
    for (int a = 0; a < 4; a++)
#pragma unroll
        for (int b = 0; b < 4; b++)
#pragma unroll
            for (int c = 0; c < 4; c++) acc[a][b][c] = 0.f;

    auto loadAB = [&](int st, int kk) {
#pragma unroll
        for (int i = 0; i < 2; i++) {
            int r = i * 64 + (tid >> 2), c = (tid & 3) * 8;
            cpa16(A0 + st * A_ST + (unsigned)(r * SA + c) * 2,
                  g_fbB + (size_t)(row0 + r) * 1024 + kk * BK + c);
        }
#pragma unroll
        for (int i = 0; i < 2; i++) {
            int r = i * 16 + (tid >> 4), c = (tid & 15) * 8;
            cpa16(B0 + st * B_ST + (unsigned)(r * SB + c) * 2,
                  g_w1B + (size_t)(kk * BK + r) * 512 + col0 + c);
        }
    };

    const int KT = 1024 / BK;
#pragma unroll
    for (int s = 0; s < STAGES - 1; s++) { loadAB(s, s); cp_commit(); }

    for (int kt = 0; kt < KT; kt++) {
        cp_wait<STAGES - 2>();
        __syncthreads();
        int kl = kt + STAGES - 1;
        if (kl < KT) loadAB(kl & (STAGES - 1), kl);
        cp_commit();
        int st = kt & (STAGES - 1);
        unsigned aS = A0 + st * A_ST + aoff;
        unsigned bS = B0 + st * B_ST + boff;
#pragma unroll
        for (int ks = 0; ks < 2; ks++) {
            unsigned afr[4][4], bfr[2][4];
#pragma unroll
            for (int mf = 0; mf < 4; mf++) ldsmx4(afr[mf], aS + mf * (16 * SA * 2) + ks * 32);
#pragma unroll
            for (int p = 0; p < 2; p++) ldsmx4t(bfr[p], bS + ks * (16 * SB * 2) + p * 32);
#pragma unroll
            for (int mf = 0; mf < 4; mf++) {
                mma16816(acc[mf][0], afr[mf], &bfr[0][0]);
                mma16816(acc[mf][1], afr[mf], &bfr[0][2]);
                mma16816(acc[mf][2], afr[mf], &bfr[1][0]);
                mma16816(acc[mf][3], afr[mf], &bfr[1][2]);
            }
        }
    }

    const int g = lane >> 2, q = lane & 3;
#pragma unroll
    for (int mf = 0; mf < 4; mf++) {
#pragma unroll
        for (int nf = 0; nf < 4; nf++) {
            int cl = col0 + wn * 32 + nf * 8 + q * 2;
#pragma unroll
            for (int i = 0; i < 4; i++) {
                int rr = row0 + wm * 64 + mf * 16 + g + ((i >= 2) ? 8 : 0);
                int cc = cl + (i & 1);
                float v = acc[mf][nf][i] + b1[cc];
                v = v > 0.f ? v : 0.01f * v;
                g_h32[(size_t)rr * 512 + cc] = v;
                g_hB [(size_t)rr * 512 + cc] = __float2bfloat16(v);
            }
        }
    }
}

// ---------------- GEMM2: B-persistent, streaming logsumexp partials ----------------
__global__ __launch_bounds__(256) void k_gemm2(const float* __restrict__ b2, int MT) {
    extern __shared__ char smem[];
    unsigned sb = (unsigned)__cvta_generic_to_shared(smem);
    const unsigned Bb = sb;
    const unsigned Ab = sb + B2_BYTES;
    float* red_m  = (float*)(smem + G2_SCR);       // [4][128]
    float* red_s  = red_m + 512;                   // [4][128]
    float* rowmax = red_s + 512;                   // [128]

    const int tid = threadIdx.x, lane = tid & 31, wid = tid >> 5;
    const int wm = wid >> 2, wn = wid & 3;
    const int g = lane >> 2, q = lane & 3;
    const int ct = blockIdx.x;
    const int col0 = ct * BN;

    // Load the full 512x128 B slice once (group 0)
#pragma unroll
    for (int i = 0; i < 32; i++) {
        int r = i * 16 + (tid >> 4), c = (tid & 15) * 8;
        cpa16(Bb + (unsigned)(r * SB + c) * 2, g_w2B + (size_t)r * TWOV + col0 + c);
    }
    cp_commit();

    const unsigned aoff = ((wm * 64 + (lane & 15)) * SA + (lane >> 4) * 8) * 2;
    const unsigned boff = ((lane & 15) * SB + wn * 32 + (lane >> 4) * 8) * 2;

    float bv[4][2];
#pragma unroll
    for (int nf = 0; nf < 4; nf++) {
        int cc = col0 + wn * 32 + nf * 8 + q * 2;
        bv[nf][0] = b2[cc];
        bv[nf][1] = b2[cc + 1];
    }

    auto loadA = [&](int st, int kk, int row0) {
#pragma unroll
        for (int i = 0; i < 2; i++) {
            int r = i * 64 + (tid >> 2), c = (tid & 3) * 8;
            cpa16(Ab + st * A_ST + (unsigned)(r * SA + c) * 2,
                  g_hB + (size_t)(row0 + r) * 512 + kk * BK + c);
        }
    };

    const int KT = 512 / BK;  // 16
    for (int rb = 0; rb < MT; rb++) {
        int row0 = rb * BM;
        float acc[4][4][4];
#pragma unroll
        for (int a = 0; a < 4; a++)
#pragma unroll
            for (int b = 0; b < 4; b++)
#pragma unroll
                for (int c = 0; c < 4; c++) acc[a][b][c] = 0.f;

#pragma unroll
        for (int s = 0; s < STAGES - 1; s++) { loadA(s, s, row0); cp_commit(); }

        for (int kt = 0; kt < KT; kt++) {
            cp_wait<STAGES - 2>();
            __syncthreads();
            int kl = kt + STAGES - 1;
            if (kl < KT) loadA(kl & (STAGES - 1), kl, row0);
            cp_commit();
            int st = kt & (STAGES - 1);
            unsigned aS = Ab + st * A_ST + aoff;
            unsigned bS = Bb + (unsigned)(kt * BK * SB) * 2 + boff;
#pragma unroll
            for (int ks = 0; ks < 2; ks++) {
                unsigned afr[4][4], bfr[2][4];
#pragma unroll
                for (int mf = 0; mf < 4; mf++) ldsmx4(afr[mf], aS + mf * (16 * SA * 2) + ks * 32);
#pragma unroll
                for (int p = 0; p < 2; p++) ldsmx4t(bfr[p], bS + ks * (16 * SB * 2) + p * 32);
#pragma unroll
                for (int mf = 0; mf < 4; mf++) {
                    mma16816(acc[mf][0], afr[mf], &bfr[0][0]);
                    mma16816(acc[mf][1], afr[mf], &bfr[0][2]);
                    mma16816(acc[mf][2], afr[mf], &bfr[1][0]);
                    mma16816(acc[mf][3], afr[mf], &bfr[1][2]);
                }
            }
        }

        // ---- epilogue: per-row tile max + sumexp partials ----
        __syncthreads();   // all ldmatrix reads done; scratch safe to write
#pragma unroll
        for (int mf = 0; mf < 4; mf++) {
#pragma unroll
            for (int rh = 0; rh < 2; rh++) {
                float m = -1e30f;
#pragma unroll
                for (int nf = 0; nf < 4; nf++) {
                    m = fmaxf(m, acc[mf][nf][rh * 2 + 0] + bv[nf][0]);
                    m = fmaxf(m, acc[mf][nf][rh * 2 + 1] + bv[nf][1]);
                }
                m = fmaxf(m, __shfl_xor_sync(0xffffffffu, m, 1));
                m = fmaxf(m, __shfl_xor_sync(0xffffffffu, m, 2));
                if (q == 0) red_m[wn * 128 + wm * 64 + mf * 16 + rh * 8 + g] = m;
            }
        }
        __syncthreads();
        if (tid < 128)
            rowmax[tid] = fmaxf(fmaxf(red_m[tid], red_m[128 + tid]),
                                fmaxf(red_m[256 + tid], red_m[384 + tid]));
        __syncthreads();
#pragma unroll
        for (int mf = 0; mf < 4; mf++) {
#pragma unroll
            for (int rh = 0; rh < 2; rh++) {
                int rl = wm * 64 + mf * 16 + rh * 8 + g;
                float rm = rowmax[rl];
                float s = 0.f;
#pragma unroll
                for (int nf = 0; nf < 4; nf++) {
                    s += __expf(acc[mf][nf][rh * 2 + 0] + bv[nf][0] - rm);
                    s += __expf(acc[mf][nf][rh * 2 + 1] + bv[nf][1] - rm);
                }
                s += __shfl_xor_sync(0xffffffffu, s, 1);
                s += __shfl_xor_sync(0xffffffffu, s, 2);
                if (q == 0) red_s[wn * 128 + rl] = s;
            }
        }
        __syncthreads();
        if (tid < 128) {
            float s = red_s[tid] + red_s[128 + tid] + red_s[256 + tid] + red_s[384 + tid];
            int rowg = row0 + tid;
            g_pm[(size_t)rowg * NT2 + ct] = rowmax[tid];
            g_ps[(size_t)rowg * NT2 + ct] = s;
        }
        __syncthreads();
    }
}

// ---------------- per-(row,branch) lse merge + label logit + nll ----------------
__global__ void k_reduce(const int* __restrict__ seq, const int* __restrict__ fi,
                         const int* __restrict__ bi, const float* __restrict__ w2,
                         const float* __restrict__ b2, int Np, int M) {
    int gw = (blockIdx.x * blockDim.x + threadIdx.x) >> 5;
    int lane = threadIdx.x & 31;
    if (gw >= M * 2) return;
    int r = gw >> 1, br = gw & 1;
    int b = r / Np, n = r - b * Np;
    int pos = br ? bi[n] : fi[n];
    int label = seq[b * L_ + pos];
    int col = br * V_ + label;

    const float* pm = g_pm + (size_t)r * NT2 + br * 250;
    const float* ps = g_ps + (size_t)r * NT2 + br * 250;
    float m = -1e30f;
    for (int i = lane; i < 250; i += 32) m = fmaxf(m, pm[i]);
#pragma unroll
    for (int o = 16; o; o >>= 1) m = fmaxf(m, __shfl_xor_sync(0xffffffffu, m, o));
    float s = 0.f;
    for (int i = lane; i < 250; i += 32) s += ps[i] * __expf(pm[i] - m);
#pragma unroll
    for (int o = 16; o; o >>= 1) s += __shfl_xor_sync(0xffffffffu, s, o);
    float lse = m + logf(s);

    float dot = 0.f;
    for (int k = lane; k < 512; k += 32)
        dot += g_h32[(size_t)r * 512 + k] * w2[(size_t)k * TWOV + col];
#pragma unroll
    for (int o = 16; o; o >>= 1) dot += __shfl_xor_sync(0xffffffffu, dot, o);

    if (lane == 0) {
        float nll = lse - (dot + b2[col]);
        g_nll[gw] = nll * (br ? 0.25f : 1.0f);
    }
}

// ---------------- deterministic final mean ----------------
__global__ void k_final(float* __restrict__ out, int M) {
    __shared__ float sh[256];
    float s = 0.f;
    for (int i = threadIdx.x; i < 2 * M; i += 256) s += g_nll[i];
    sh[threadIdx.x] = s;
    __syncthreads();
    for (int o = 128; o; o >>= 1) {
        if (threadIdx.x < o) sh[threadIdx.x] += sh[threadIdx.x + o];
        __syncthreads();
    }
    if (threadIdx.x == 0) out[0] = sh[0] / (float)(2 * M);
}

// ---------------- launch ----------------
extern "C" void kernel_launch(void* const* d_in, const int* in_sizes, int n_in,
                              void* d_out, int out_size) {
    const float* fwd = (const float*)d_in[0];
    const float* bwd = (const float*)d_in[1];
    const int*   seq = (const int*)  d_in[2];
    const int*   fi  = (const int*)  d_in[3];
    const int*   bi  = (const int*)  d_in[4];
    const float* w1  = (const float*)d_in[5];
    const float* b1  = (const float*)d_in[6];
    const float* w2  = (const float*)d_in[7];
    const float* b2  = (const float*)d_in[8];

    int Np = in_sizes[3];
    int M  = B_ * Np;
    int MT = (M + BM - 1) / BM;
    int Mpad = MT * BM;

    cudaFuncSetAttribute(k_gemm1, cudaFuncAttributeMaxDynamicSharedMemorySize, G1_SMEM);
    cudaFuncSetAttribute(k_gemm2, cudaFuncAttributeMaxDynamicSharedMemorySize, G2_SMEM);

    k_f2bf<<<256, 256>>>(w1, 0, (1024 * 512) / 4);
    k_f2bf<<<2048, 256>>>(w2, 1, (512 * TWOV) / 4);
    k_gather<<<Mpad, 256>>>(fwd, bwd, fi, bi, Np, M);

    dim3 g1(512 / BN, MT);
    k_gemm1<<<g1, 256, G1_SMEM>>>(b1);

    k_gemm2<<<NT2, 256, G2_SMEM>>>(b2, MT);

    int warps = M * 2;
    int blocks = (warps * 32 + 255) / 256;
    k_reduce<<<blocks, 256>>>(seq, fi, bi, w2, b2, Np, M);
    k_final<<<1, 256>>>((float*)d_out, M);
}

// round 5
// speedup vs baseline: 2.7945x; 1.1425x over previous
#include <cuda_runtime.h>
#include <cuda_bf16.h>
#include <cstdint>

// Problem constants
#define B_    2
#define L_    512
#define V_    32000
#define TWOV  64000
#define MAXM  4096
#define NT2   500            // 64000/128 vocab tiles

// ---------------- GEMM1 (mma.sync) tiling ----------------
#define BM 128
#define BN 128
#define BK 32
#define SA 40
#define SB 136
#define STAGES 4
#define A_ST (BM * SA * 2)
#define B_ST (BK * SB * 2)
#define G1_SMEM (STAGES * (A_ST + B_ST))

// ---------------- GEMM2 (mma.sync, 512 threads, BK=64, B-persistent) ----------------
#define SA2 72                         // 64 + 8 pad (144B stride, conflict-free)
#define A2_ST (128 * SA2 * 2)          // 18432 B per A stage
#define B2_BYTES (512 * SB * 2)        // 139264 (full 512K x 128N slice)
#define G2_SCR (B2_BYTES + 4 * A2_ST)  // 212992
#define G2_SMEM (G2_SCR + 4608)        // 217600  (<= 232448)

// ---------------- device scratch ----------------
static __device__ __align__(256) __nv_bfloat16 g_fbB[MAXM * 1024];
static __device__ __align__(256) __nv_bfloat16 g_w1B[1024 * 512];
static __device__ __align__(256) __nv_bfloat16 g_w2B[512 * TWOV];
static __device__ __align__(256) float         g_h32[MAXM * 512];
static __device__ __align__(256) __nv_bfloat16 g_hB [MAXM * 512];
static __device__ __align__(256) float         g_pm [MAXM * NT2];
static __device__ __align__(256) float         g_ps [MAXM * NT2];
static __device__ __align__(256) float         g_nll[MAXM * 2];

// ---------------- PTX helpers ----------------
__device__ __forceinline__ void cpa16(unsigned s, const void* g) {
    asm volatile("cp.async.cg.shared.global [%0], [%1], 16;\n" :: "r"(s), "l"(g));
}
__device__ __forceinline__ void cp_commit() { asm volatile("cp.async.commit_group;\n"); }
template<int N> __device__ __forceinline__ void cp_wait() {
    asm volatile("cp.async.wait_group %0;\n" :: "n"(N));
}
__device__ __forceinline__ void ldsmx4(unsigned* r, unsigned a) {
    asm volatile("ldmatrix.sync.aligned.m8n8.x4.shared.b16 {%0,%1,%2,%3}, [%4];\n"
                 : "=r"(r[0]), "=r"(r[1]), "=r"(r[2]), "=r"(r[3]) : "r"(a));
}
__device__ __forceinline__ void ldsmx4t(unsigned* r, unsigned a) {
    asm volatile("ldmatrix.sync.aligned.m8n8.x4.trans.shared.b16 {%0,%1,%2,%3}, [%4];\n"
                 : "=r"(r[0]), "=r"(r[1]), "=r"(r[2]), "=r"(r[3]) : "r"(a));
}
__device__ __forceinline__ void mma16816(float* c, const unsigned* a, const unsigned* b) {
    asm volatile(
        "mma.sync.aligned.m16n8k16.row.col.f32.bf16.bf16.f32 "
        "{%0,%1,%2,%3}, {%4,%5,%6,%7}, {%8,%9}, {%0,%1,%2,%3};\n"
        : "+f"(c[0]), "+f"(c[1]), "+f"(c[2]), "+f"(c[3])
        : "r"(a[0]), "r"(a[1]), "r"(a[2]), "r"(a[3]), "r"(b[0]), "r"(b[1]));
}

// ---------------- fp32 -> bf16 weight conversion ----------------
__global__ void k_f2bf(const float* __restrict__ src, int which, int n4) {
    __nv_bfloat16* dst = which ? g_w2B : g_w1B;
    int i = blockIdx.x * blockDim.x + threadIdx.x;
    int stride = gridDim.x * blockDim.x;
    for (; i < n4; i += stride) {
        float4 v = reinterpret_cast<const float4*>(src)[i];
        reinterpret_cast<__nv_bfloat162*>(dst)[2 * i]     = __floats2bfloat162_rn(v.x, v.y);
        reinterpret_cast<__nv_bfloat162*>(dst)[2 * i + 1] = __floats2bfloat162_rn(v.z, v.w);
    }
}

// ---------------- gather fb rows -> bf16, zero-pad ----------------
__global__ void k_gather(const float* __restrict__ fwd, const float* __restrict__ bwd,
                         const int* __restrict__ fi, const int* __restrict__ bi,
                         int Np, int M) {
    int row = blockIdx.x;
    if (row < M) {
        int b = row / Np;
        int n = row - b * Np;
        const float* fsrc = fwd + ((size_t)b * L_ + fi[n]) * 512;
        const float* bsrc = bwd + ((size_t)b * L_ + bi[n]) * 512;
        for (int c = threadIdx.x; c < 1024; c += blockDim.x) {
            float v = (c < 512) ? fsrc[c] : bsrc[c - 512];
            g_fbB[(size_t)row * 1024 + c] = __float2bfloat16(v);
        }
    } else {
        for (int c = threadIdx.x; c < 1024; c += blockDim.x)
            g_fbB[(size_t)row * 1024 + c] = __float2bfloat16(0.f);
    }
}

// ---------------- GEMM1: h = leaky_relu(fb @ w1 + b1)  (mma.sync, 256 thr) ----------------
__global__ __launch_bounds__(256) void k_gemm1(const float* __restrict__ b1) {
    extern __shared__ char smem[];
    unsigned sb = (unsigned)__cvta_generic_to_shared(smem);
    const unsigned A0 = sb;
    const unsigned B0 = sb + STAGES * A_ST;
    const int tid = threadIdx.x, lane = tid & 31, wid = tid >> 5;
    const int wm = wid >> 2, wn = wid & 3;
    const int row0 = blockIdx.y * BM, col0 = blockIdx.x * BN;

    const unsigned aoff = ((wm * 64 + (lane & 15)) * SA + (lane >> 4) * 8) * 2;
    const unsigned boff = ((lane & 15) * SB + wn * 32 + (lane >> 4) * 8) * 2;

    float acc[4][4][4];
#pragma unroll
    for (int a = 0; a < 4; a++)
#pragma unroll
        for (int b = 0; b < 4; b++)
#pragma unroll
            for (int c = 0; c < 4; c++) acc[a][b][c] = 0.f;

    auto loadAB = [&](int st, int kk) {
#pragma unroll
        for (int i = 0; i < 2; i++) {
            int r = i * 64 + (tid >> 2), c = (tid & 3) * 8;
            cpa16(A0 + st * A_ST + (unsigned)(r * SA + c) * 2,
                  g_fbB + (size_t)(row0 + r) * 1024 + kk * BK + c);
        }
#pragma unroll
        for (int i = 0; i < 2; i++) {
            int r = i * 16 + (tid >> 4), c = (tid & 15) * 8;
            cpa16(B0 + st * B_ST + (unsigned)(r * SB + c) * 2,
                  g_w1B + (size_t)(kk * BK + r) * 512 + col0 + c);
        }
    };

    const int KT = 1024 / BK;
#pragma unroll
    for (int s = 0; s < STAGES - 1; s++) { loadAB(s, s); cp_commit(); }

    for (int kt = 0; kt < KT; kt++) {
        cp_wait<STAGES - 2>();
        __syncthreads();
        int kl = kt + STAGES - 1;
        if (kl < KT) loadAB(kl & (STAGES - 1), kl);
        cp_commit();
        int st = kt & (STAGES - 1);
        unsigned aS = A0 + st * A_ST + aoff;
        unsigned bS = B0 + st * B_ST + boff;
#pragma unroll
        for (int ks = 0; ks < 2; ks++) {
            unsigned afr[4][4], bfr[2][4];
#pragma unroll
            for (int mf = 0; mf < 4; mf++) ldsmx4(afr[mf], aS + mf * (16 * SA * 2) + ks * 32);
#pragma unroll
            for (int p = 0; p < 2; p++) ldsmx4t(bfr[p], bS + ks * (16 * SB * 2) + p * 32);
#pragma unroll
            for (int mf = 0; mf < 4; mf++) {
                mma16816(acc[mf][0], afr[mf], &bfr[0][0]);
                mma16816(acc[mf][1], afr[mf], &bfr[0][2]);
                mma16816(acc[mf][2], afr[mf], &bfr[1][0]);
                mma16816(acc[mf][3], afr[mf], &bfr[1][2]);
            }
        }
    }

    const int g = lane >> 2, q = lane & 3;
#pragma unroll
    for (int mf = 0; mf < 4; mf++) {
#pragma unroll
        for (int nf = 0; nf < 4; nf++) {
            int cl = col0 + wn * 32 + nf * 8 + q * 2;
#pragma unroll
            for (int i = 0; i < 4; i++) {
                int rr = row0 + wm * 64 + mf * 16 + g + ((i >= 2) ? 8 : 0);
                int cc = cl + (i & 1);
                float v = acc[mf][nf][i] + b1[cc];
                v = v > 0.f ? v : 0.01f * v;
                g_h32[(size_t)rr * 512 + cc] = v;
                g_hB [(size_t)rr * 512 + cc] = __float2bfloat16(v);
            }
        }
    }
}

// ---------------- GEMM2: 512 thr / 16 warps, BK=64, B-persistent, streaming lse ----------------
__global__ __launch_bounds__(512, 1) void k_gemm2(const float* __restrict__ b2, int MT) {
    extern __shared__ char smem[];
    unsigned sb = (unsigned)__cvta_generic_to_shared(smem);
    const unsigned Bb = sb;
    const unsigned Ab = sb + B2_BYTES;
    float* red_m  = (float*)(smem + G2_SCR);   // [4][128]
    float* red_s  = red_m + 512;               // [4][128]
    float* rowmax = red_s + 512;               // [128]

    const int tid = threadIdx.x, lane = tid & 31, wid = tid >> 5;
    const int wm = wid >> 2, wn = wid & 3;          // 4x4 warp grid, 32x32 per warp
    const int g = lane >> 2, q = lane & 3;
    const int ct = blockIdx.x;
    const int col0 = ct * 128;

    // Load persistent B slice: 512 K-rows x 128 N-cols bf16 (group 0)
    for (int i = tid; i < 8192; i += 512) {
        int r = i >> 4, c = (i & 15) * 8;
        cpa16(Bb + (unsigned)(r * SB + c) * 2, g_w2B + (size_t)r * TWOV + col0 + c);
    }
    cp_commit();

    const unsigned aoff = ((wm * 32 + (lane & 15)) * SA2 + (lane >> 4) * 8) * 2;
    const unsigned boff = ((lane & 15) * SB + wn * 32 + (lane >> 4) * 8) * 2;

    float bv[4][2];
#pragma unroll
    for (int nf = 0; nf < 4; nf++) {
        int cc = col0 + wn * 32 + nf * 8 + q * 2;
        bv[nf][0] = b2[cc];
        bv[nf][1] = b2[cc + 1];
    }

    // A-stage loader, global chunk index c = rb*8 + kt (128 rows x 64 K-cols)
    auto loadA = [&](int st, int cidx) {
        int rb = cidx >> 3, kt = cidx & 7;
        const __nv_bfloat16* base = g_hB + (size_t)(rb * 128) * 512 + kt * 64;
#pragma unroll
        for (int i = 0; i < 2; i++) {
            int idx = tid + i * 512;
            int r = idx >> 3, c = (idx & 7) * 8;
            cpa16(Ab + st * A2_ST + (unsigned)(r * SA2 + c) * 2, base + (size_t)r * 512 + c);
        }
    };

    const int T = MT * 8;
#pragma unroll
    for (int s = 0; s < 3; s++) { loadA(s, s); cp_commit(); }

    int c = 0;
    for (int rb = 0; rb < MT; rb++) {
        float acc[2][4][4];
#pragma unroll
        for (int a = 0; a < 2; a++)
#pragma unroll
            for (int b = 0; b < 4; b++)
#pragma unroll
                for (int e = 0; e < 4; e++) acc[a][b][e] = 0.f;

        for (int kt = 0; kt < 8; kt++, c++) {
            cp_wait<2>();
            __syncthreads();
            int cl = c + 3;
            if (cl < T) loadA(cl & 3, cl);
            cp_commit();
            unsigned aS = Ab + (c & 3) * A2_ST + aoff;
            unsigned bS = Bb + (unsigned)(kt * 64 * SB) * 2 + boff;
#pragma unroll
            for (int ks = 0; ks < 4; ks++) {
                unsigned afr[2][4], bfr[2][4];
#pragma unroll
                for (int mf = 0; mf < 2; mf++)
                    ldsmx4(afr[mf], aS + mf * (16 * SA2 * 2) + ks * 32);
#pragma unroll
                for (int p = 0; p < 2; p++)
                    ldsmx4t(bfr[p], bS + ks * (16 * SB * 2) + p * 32);
#pragma unroll
                for (int mf = 0; mf < 2; mf++) {
                    mma16816(acc[mf][0], afr[mf], &bfr[0][0]);
                    mma16816(acc[mf][1], afr[mf], &bfr[0][2]);
                    mma16816(acc[mf][2], afr[mf], &bfr[1][0]);
                    mma16816(acc[mf][3], afr[mf], &bfr[1][2]);
                }
            }
        }

        // ---- epilogue: per-row tile max + sumexp partials (next block's A in flight) ----
        __syncthreads();
#pragma unroll
        for (int mf = 0; mf < 2; mf++) {
#pragma unroll
            for (int rh = 0; rh < 2; rh++) {
                float m = -1e30f;
#pragma unroll
                for (int nf = 0; nf < 4; nf++) {
                    m = fmaxf(m, acc[mf][nf][rh * 2 + 0] + bv[nf][0]);
                    m = fmaxf(m, acc[mf][nf][rh * 2 + 1] + bv[nf][1]);
                }
                m = fmaxf(m, __shfl_xor_sync(0xffffffffu, m, 1));
                m = fmaxf(m, __shfl_xor_sync(0xffffffffu, m, 2));
                if (q == 0) red_m[wn * 128 + wm * 32 + mf * 16 + rh * 8 + g] = m;
            }
        }
        __syncthreads();
        if (tid < 128)
            rowmax[tid] = fmaxf(fmaxf(red_m[tid], red_m[128 + tid]),
                                fmaxf(red_m[256 + tid], red_m[384 + tid]));
        __syncthreads();
#pragma unroll
        for (int mf = 0; mf < 2; mf++) {
#pragma unroll
            for (int rh = 0; rh < 2; rh++) {
                int rl = wm * 32 + mf * 16 + rh * 8 + g;
                float rm = rowmax[rl];
                float s = 0.f;
#pragma unroll
                for (int nf = 0; nf < 4; nf++) {
                    s += __expf(acc[mf][nf][rh * 2 + 0] + bv[nf][0] - rm);
                    s += __expf(acc[mf][nf][rh * 2 + 1] + bv[nf][1] - rm);
                }
                s += __shfl_xor_sync(0xffffffffu, s, 1);
                s += __shfl_xor_sync(0xffffffffu, s, 2);
                if (q == 0) red_s[wn * 128 + rl] = s;
            }
        }
        __syncthreads();
        if (tid < 128) {
            float s = red_s[tid] + red_s[128 + tid] + red_s[256 + tid] + red_s[384 + tid];
            int rowg = rb * 128 + tid;
            g_pm[(size_t)rowg * NT2 + ct] = rowmax[tid];
            g_ps[(size_t)rowg * NT2 + ct] = s;
        }
        __syncthreads();
    }
}

// ---------------- per-(row,branch) lse merge + label logit + nll ----------------
__global__ void k_reduce(const int* __restrict__ seq, const int* __restrict__ fi,
                         const int* __restrict__ bi, const float* __restrict__ w2,
                         const float* __restrict__ b2, int Np, int M) {
    int gw = (blockIdx.x * blockDim.x + threadIdx.x) >> 5;
    int lane = threadIdx.x & 31;
    if (gw >= M * 2) return;
    int r = gw >> 1, br = gw & 1;
    int b = r / Np, n = r - b * Np;
    int pos = br ? bi[n] : fi[n];
    int label = seq[b * L_ + pos];
    int col = br * V_ + label;

    const float* pm = g_pm + (size_t)r * NT2 + br * 250;
    const float* ps = g_ps + (size_t)r * NT2 + br * 250;
    float m = -1e30f;
    for (int i = lane; i < 250; i += 32) m = fmaxf(m, pm[i]);
#pragma unroll
    for (int o = 16; o; o >>= 1) m = fmaxf(m, __shfl_xor_sync(0xffffffffu, m, o));
    float s = 0.f;
    for (int i = lane; i < 250; i += 32) s += ps[i] * __expf(pm[i] - m);
#pragma unroll
    for (int o = 16; o; o >>= 1) s += __shfl_xor_sync(0xffffffffu, s, o);
    float lse = m + logf(s);

    float dot = 0.f;
    for (int k = lane; k < 512; k += 32)
        dot += g_h32[(size_t)r * 512 + k] * w2[(size_t)k * TWOV + col];
#pragma unroll
    for (int o = 16; o; o >>= 1) dot += __shfl_xor_sync(0xffffffffu, dot, o);

    if (lane == 0) {
        float nll = lse - (dot + b2[col]);
        g_nll[gw] = nll * (br ? 0.25f : 1.0f);
    }
}

// ---------------- deterministic final mean ----------------
__global__ void k_final(float* __restrict__ out, int M) {
    __shared__ float sh[256];
    float s = 0.f;
    for (int i = threadIdx.x; i < 2 * M; i += 256) s += g_nll[i];
    sh[threadIdx.x] = s;
    __syncthreads();
    for (int o = 128; o; o >>= 1) {
        if (threadIdx.x < o) sh[threadIdx.x] += sh[threadIdx.x + o];
        __syncthreads();
    }
    if (threadIdx.x == 0) out[0] = sh[0] / (float)(2 * M);
}

// ---------------- launch ----------------
extern "C" void kernel_launch(void* const* d_in, const int* in_sizes, int n_in,
                              void* d_out, int out_size) {
    const float* fwd = (const float*)d_in[0];
    const float* bwd = (const float*)d_in[1];
    const int*   seq = (const int*)  d_in[2];
    const int*   fi  = (const int*)  d_in[3];
    const int*   bi  = (const int*)  d_in[4];
    const float* w1  = (const float*)d_in[5];
    const float* b1  = (const float*)d_in[6];
    const float* w2  = (const float*)d_in[7];
    const float* b2  = (const float*)d_in[8];

    int Np = in_sizes[3];
    int M  = B_ * Np;
    int MT = (M + BM - 1) / BM;
    int Mpad = MT * BM;

    cudaFuncSetAttribute(k_gemm1, cudaFuncAttributeMaxDynamicSharedMemorySize, G1_SMEM);
    cudaFuncSetAttribute(k_gemm2, cudaFuncAttributeMaxDynamicSharedMemorySize, G2_SMEM);

    k_f2bf<<<256, 256>>>(w1, 0, (1024 * 512) / 4);
    k_f2bf<<<2048, 256>>>(w2, 1, (512 * TWOV) / 4);
    k_gather<<<Mpad, 256>>>(fwd, bwd, fi, bi, Np, M);

    dim3 g1(512 / BN, MT);
    k_gemm1<<<g1, 256, G1_SMEM>>>(b1);

    k_gemm2<<<NT2, 512, G2_SMEM>>>(b2, MT);

    int warps = M * 2;
    int blocks = (warps * 32 + 255) / 256;
    k_reduce<<<blocks, 256>>>(seq, fi, bi, w2, b2, Np, M);
    k_final<<<1, 256>>>((float*)d_out, M);
}